// round 12
// baseline (speedup 1.0000x reference)
#include <cuda_runtime.h>
#include <cuda_bf16.h>
#include <stdint.h>

#define NNODE 1000000
#define NEDGE 8000000

// Scratch in __device__ globals (zero-initialized at module load; g_deg is
// re-zeroed by k_final each run -> self-cleaning, no k_zero pass).
__device__ float  g_deg [NNODE];   // in-degree at dst; zeroed in k_final
__device__ float  g_dinv[NNODE];   // rsqrt(deg + 1)
__device__ float4 g_xs  [NNODE];   // x * dinv
__device__ float4 g_acc1[NNODE];   // layer-1 accumulator; zeroed in k_prep
__device__ float2 g_gs  [NNODE];   // (relu(A1 x W1 + b1) W2) * dinv
__device__ float2 g_acc2[NNODE];   // layer-2 accumulator; zeroed in k_mid

// ---------------------------------------------------------------------------
// PDL intrinsics
__device__ __forceinline__ void pdl_wait() {
    asm volatile("griddepcontrol.wait;" ::: "memory");
}
__device__ __forceinline__ void pdl_trigger() {
    asm volatile("griddepcontrol.launch_dependents;" ::: "memory");
}

__device__ __forceinline__ void red_v4(float4* p, float4 v) {
    asm volatile("red.global.add.v4.f32 [%0], {%1,%2,%3,%4};"
                 :: "l"(p), "f"(v.x), "f"(v.y), "f"(v.z), "f"(v.w) : "memory");
}
__device__ __forceinline__ void red_v2(float2* p, float2 v) {
    asm volatile("red.global.add.v2.f32 [%0], {%1,%2};"
                 :: "l"(p), "f"(v.x), "f"(v.y) : "memory");
}
__device__ __forceinline__ float4 ldcg_f4(const float4* p) { return __ldcg(p); }
__device__ __forceinline__ float2 ldcg_f2(const float2* p) { return __ldcg(p); }

// packed f32x2 helpers (sm_103a FFMA2 path)
#define PACK2(out, lo, hi) \
    asm("mov.b64 %0, {%1, %2};" : "=l"(out) : "f"(lo), "f"(hi))
#define UNPACK2(lo, hi, in) \
    asm("mov.b64 {%0, %1}, %2;" : "=f"(lo), "=f"(hi) : "l"(in))
#define FMA2(d, a, b, c) \
    asm("fma.rn.f32x2 %0, %1, %2, %3;" : "=l"(d) : "l"(a), "l"(b), "l"(c))

// ---------------------------------------------------------------------------
// 1. in-degree at dst — 4 edges/thread
__global__ void __launch_bounds__(256) k_deg(const int* __restrict__ dst, int e) {
    pdl_wait();
    int base = (blockIdx.x * blockDim.x + threadIdx.x) * 4;
    if (base + 4 <= e) {
        int4 d = *(const int4*)(dst + base);
        atomicAdd(&g_deg[d.x], 1.0f);
        atomicAdd(&g_deg[d.y], 1.0f);
        atomicAdd(&g_deg[d.z], 1.0f);
        atomicAdd(&g_deg[d.w], 1.0f);
    } else {
        for (int i = base; i < e; i++) atomicAdd(&g_deg[dst[i]], 1.0f);
    }
    pdl_trigger();
}

// ---------------------------------------------------------------------------
// 2. dinv + pre-scaled features; zeros acc1
__global__ void __launch_bounds__(256) k_prep(const float4* __restrict__ x, int n) {
    pdl_wait();
    int i = blockIdx.x * blockDim.x + threadIdx.x;
    if (i < n) {
        float di = rsqrtf(g_deg[i] + 1.0f);   // self-loop -> deg >= 1
        g_dinv[i] = di;
        float4 v = x[i];
        v.x *= di; v.y *= di; v.z *= di; v.w *= di;
        g_xs[i]   = v;
        g_acc1[i] = make_float4(0.f, 0.f, 0.f, 0.f);
    }
    pdl_trigger();
}

// ---------------------------------------------------------------------------
// 3. layer-1 scatter: acc1[dst] += xs[src] — 4 edges/thread
__global__ void __launch_bounds__(256) k_scatter1(const int* __restrict__ src,
                                                  const int* __restrict__ dst, int e) {
    pdl_wait();
    int base = (blockIdx.x * blockDim.x + threadIdx.x) * 4;
    if (base + 4 <= e) {
        int4 s = *(const int4*)(src + base);
        int4 d = *(const int4*)(dst + base);
        float4 v0 = ldcg_f4(&g_xs[s.x]);
        float4 v1 = ldcg_f4(&g_xs[s.y]);
        float4 v2 = ldcg_f4(&g_xs[s.z]);
        float4 v3 = ldcg_f4(&g_xs[s.w]);
        red_v4(&g_acc1[d.x], v0);
        red_v4(&g_acc1[d.y], v1);
        red_v4(&g_acc1[d.z], v2);
        red_v4(&g_acc1[d.w], v3);
    } else {
        for (int i = base; i < e; i++)
            red_v4(&g_acc1[dst[i]], ldcg_f4(&g_xs[src[i]]));
    }
    pdl_trigger();
}

// ---------------------------------------------------------------------------
// 4. fused node transform; zeros acc2.
//    2 nodes/thread packed as f32x2 lanes; weights pre-duplicated in smem as
//    packed {w,w} u64 pairs -> inner loop has ZERO pack movs:
//    3x LDS.128 + 1x LDS.64 + 6x FFMA2 + relu per j for TWO nodes.
//    Per-node fma order identical to the scalar reference.
__global__ void __launch_bounds__(256) k_mid(const float* __restrict__ W1,   // [4,64]
                                             const float* __restrict__ b1,   // [64]
                                             const float* __restrict__ W2,   // [64,2]
                                             int n) {
    __shared__ ulonglong2          sP[64];  // { {w0j,w0j}, {w1j,w1j} }
    __shared__ ulonglong2          sQ[64];  // { {w2j,w2j}, {w3j,w3j} }
    __shared__ ulonglong2          sR[64];  // { {bj,bj},   {c0j,c0j} }
    __shared__ unsigned long long  sS[64];  // { {c1j,c1j} }
    int t = threadIdx.x;
    if (t < 64) {
        float w0 = W1[t], w1 = W1[64 + t], w2 = W1[128 + t], w3 = W1[192 + t];
        float bb = b1[t], c0 = W2[2 * t], c1 = W2[2 * t + 1];
        unsigned long long p0, p1, p2, p3, pb, pc, pd;
        PACK2(p0, w0, w0); PACK2(p1, w1, w1);
        PACK2(p2, w2, w2); PACK2(p3, w3, w3);
        PACK2(pb, bb, bb); PACK2(pc, c0, c0); PACK2(pd, c1, c1);
        sP[t] = make_ulonglong2(p0, p1);
        sQ[t] = make_ulonglong2(p2, p3);
        sR[t] = make_ulonglong2(pb, pc);
        sS[t] = pd;
    }
    pdl_wait();
    __syncthreads();

    int i = blockIdx.x * blockDim.x + t;      // node-pair index
    if (i >= (n >> 1)) return;                // n = 1M, even
    int i0 = 2 * i;

    float2 dd = *(const float2*)&g_dinv[i0];
    float4 aA = g_acc1[i0], aB = g_acc1[i0 + 1];
    float4 xA = g_xs[i0],   xB = g_xs[i0 + 1];

    float a0A = dd.x * (aA.x + xA.x), a0B = dd.y * (aB.x + xB.x);
    float a1A = dd.x * (aA.y + xA.y), a1B = dd.y * (aB.y + xB.y);
    float a2A = dd.x * (aA.z + xA.z), a2B = dd.y * (aB.z + xB.z);
    float a3A = dd.x * (aA.w + xA.w), a3B = dd.y * (aB.w + xB.w);

    unsigned long long pa0, pa1, pa2, pa3, po0, po1;
    PACK2(pa0, a0A, a0B);
    PACK2(pa1, a1A, a1B);
    PACK2(pa2, a2A, a2B);
    PACK2(pa3, a3A, a3B);
    PACK2(po0, 0.f, 0.f);
    PACK2(po1, 0.f, 0.f);

#pragma unroll
    for (int j = 0; j < 64; j++) {
        ulonglong2 P = sP[j];
        ulonglong2 Q = sQ[j];
        ulonglong2 R = sR[j];
        unsigned long long S = sS[j];
        unsigned long long h2 = R.x;          // {b1[j], b1[j]}
        FMA2(h2, pa0, P.x, h2);
        FMA2(h2, pa1, P.y, h2);
        FMA2(h2, pa2, Q.x, h2);
        FMA2(h2, pa3, Q.y, h2);
        float hl, hh;
        UNPACK2(hl, hh, h2);                  // reg-pair alias, ~free
        hl = fmaxf(hl, 0.f);
        hh = fmaxf(hh, 0.f);
        PACK2(h2, hl, hh);
        FMA2(po0, h2, R.y, po0);              // o0 += h * W2[j][0]
        FMA2(po1, h2, S,   po1);              // o1 += h * W2[j][1]
    }
    float o0A, o0B, o1A, o1B;
    UNPACK2(o0A, o0B, po0);
    UNPACK2(o1A, o1B, po1);

    float4* gsp  = (float4*)&g_gs[i0];        // two consecutive float2 -> one STG.128
    float4* ac2p = (float4*)&g_acc2[i0];
    *gsp  = make_float4(o0A * dd.x, o1A * dd.x, o0B * dd.y, o1B * dd.y);
    *ac2p = make_float4(0.f, 0.f, 0.f, 0.f);
    pdl_trigger();
}

// ---------------------------------------------------------------------------
// 5. layer-2 scatter: acc2[dst] += gs[src] — 4 edges/thread
__global__ void __launch_bounds__(256) k_scatter2(const int* __restrict__ src,
                                                  const int* __restrict__ dst, int e) {
    pdl_wait();
    int base = (blockIdx.x * blockDim.x + threadIdx.x) * 4;
    if (base + 4 <= e) {
        int4 s = *(const int4*)(src + base);
        int4 d = *(const int4*)(dst + base);
        float2 v0 = ldcg_f2(&g_gs[s.x]);
        float2 v1 = ldcg_f2(&g_gs[s.y]);
        float2 v2 = ldcg_f2(&g_gs[s.z]);
        float2 v3 = ldcg_f2(&g_gs[s.w]);
        red_v2(&g_acc2[d.x], v0);
        red_v2(&g_acc2[d.y], v1);
        red_v2(&g_acc2[d.z], v2);
        red_v2(&g_acc2[d.w], v3);
    } else {
        for (int i = base; i < e; i++)
            red_v2(&g_acc2[dst[i]], ldcg_f2(&g_gs[src[i]]));
    }
    pdl_trigger();
}

// ---------------------------------------------------------------------------
// 6. final: out = dinv * (acc2 + gs) + b2; re-zeroes deg for the next run
__global__ void __launch_bounds__(256) k_final(const float* __restrict__ b2,
                                               float2* __restrict__ out, int n) {
    float bx = __ldg(&b2[0]);
    float by = __ldg(&b2[1]);
    pdl_wait();
    int i = blockIdx.x * blockDim.x + threadIdx.x;
    if (i < n) {
        float di = g_dinv[i];
        float2 a = g_acc2[i];
        float2 g = g_gs[i];
        out[i] = make_float2(di * (a.x + g.x) + bx,
                             di * (a.y + g.y) + by);
        g_deg[i] = 0.0f;   // self-clean: ready for next invocation/replay
    }
}

// ---------------------------------------------------------------------------
// PDL launch helper
template <typename... Args>
static void pdl_launch(void (*kern)(Args...), int grid, int block,
                       Args... args) {
    cudaLaunchConfig_t cfg = {};
    cfg.gridDim  = dim3(grid, 1, 1);
    cfg.blockDim = dim3(block, 1, 1);
    cfg.dynamicSmemBytes = 0;
    cfg.stream = 0;
    cudaLaunchAttribute attr[1];
    attr[0].id = cudaLaunchAttributeProgrammaticStreamSerialization;
    attr[0].val.programmaticStreamSerializationAllowed = 1;
    cfg.attrs = attr;
    cfg.numAttrs = 1;
    cudaLaunchKernelEx(&cfg, kern, args...);
}

extern "C" void kernel_launch(void* const* d_in, const int* in_sizes, int n_in,
                              void* d_out, int out_size) {
    const float* x  = (const float*)d_in[0];   // [N,4]
    const int*   ei = (const int*)d_in[1];     // [2,E]  int32
    const float* W1 = (const float*)d_in[2];   // [4,64]
    const float* b1 = (const float*)d_in[3];   // [64]
    const float* W2 = (const float*)d_in[4];   // [64,2]
    const float* b2 = (const float*)d_in[5];   // [2]
    float2*      out = (float2*)d_out;         // [N,2]

    const int n = in_sizes[0] / 4;
    const int e = in_sizes[1] / 2;
    const int* src = ei;
    const int* dst = ei + e;

    const int T = 256;
    const int gn  = (n + T - 1) / T;
    const int gnh = (n / 2 + T - 1) / T;         // node pairs (k_mid)
    const int ge4 = ((e + 3) / 4 + T - 1) / T;   // 4 edges/thread

    pdl_launch(k_deg,      ge4, T, dst, e);
    pdl_launch(k_prep,     gn,  T, (const float4*)x, n);
    pdl_launch(k_scatter1, ge4, T, src, dst, e);
    pdl_launch(k_mid,      gnh, T, W1, b1, W2, n);
    pdl_launch(k_scatter2, ge4, T, src, dst, e);
    pdl_launch(k_final,    gn,  T, b2, out, n);
}

// round 13
// speedup vs baseline: 1.0333x; 1.0333x over previous
#include <cuda_runtime.h>
#include <cuda_bf16.h>
#include <stdint.h>

#define NNODE 1000000
#define NEDGE 8000000

// Scratch in __device__ globals (zero-initialized at module load; g_deg is
// re-zeroed by k_final each run -> self-cleaning, no k_zero pass).
__device__ float  g_deg [NNODE];   // in-degree at dst; zeroed in k_final
__device__ float  g_dinv[NNODE];   // rsqrt(deg + 1)
__device__ float4 g_xs  [NNODE];   // x * dinv (gather source for scatter1)
__device__ float4 g_acc1[NNODE];   // layer-1 acc; INIT = xs (self-loop folded in)
__device__ float2 g_gs  [NNODE];   // (relu(.) W2) * dinv (gather source for scatter2)
__device__ float2 g_acc2[NNODE];   // layer-2 acc; INIT = gs (self-loop folded in)

// ---------------------------------------------------------------------------
// PDL intrinsics
__device__ __forceinline__ void pdl_wait() {
    asm volatile("griddepcontrol.wait;" ::: "memory");
}
__device__ __forceinline__ void pdl_trigger() {
    asm volatile("griddepcontrol.launch_dependents;" ::: "memory");
}

__device__ __forceinline__ void red_v4(float4* p, float4 v) {
    asm volatile("red.global.add.v4.f32 [%0], {%1,%2,%3,%4};"
                 :: "l"(p), "f"(v.x), "f"(v.y), "f"(v.z), "f"(v.w) : "memory");
}
__device__ __forceinline__ void red_v2(float2* p, float2 v) {
    asm volatile("red.global.add.v2.f32 [%0], {%1,%2};"
                 :: "l"(p), "f"(v.x), "f"(v.y) : "memory");
}
__device__ __forceinline__ float4 ldcg_f4(const float4* p) { return __ldcg(p); }
__device__ __forceinline__ float2 ldcg_f2(const float2* p) { return __ldcg(p); }

// packed f32x2 helpers (sm_103a FFMA2 path)
#define PACK2(out, lo, hi) \
    asm("mov.b64 %0, {%1, %2};" : "=l"(out) : "f"(lo), "f"(hi))
#define UNPACK2(lo, hi, in) \
    asm("mov.b64 {%0, %1}, %2;" : "=f"(lo), "=f"(hi) : "l"(in))
#define FMA2(d, a, b, c) \
    asm("fma.rn.f32x2 %0, %1, %2, %3;" : "=l"(d) : "l"(a), "l"(b), "l"(c))

// ---------------------------------------------------------------------------
// 1. in-degree at dst — 4 edges/thread
__global__ void __launch_bounds__(256) k_deg(const int* __restrict__ dst, int e) {
    pdl_wait();
    int base = (blockIdx.x * blockDim.x + threadIdx.x) * 4;
    if (base + 4 <= e) {
        int4 d = *(const int4*)(dst + base);
        atomicAdd(&g_deg[d.x], 1.0f);
        atomicAdd(&g_deg[d.y], 1.0f);
        atomicAdd(&g_deg[d.z], 1.0f);
        atomicAdd(&g_deg[d.w], 1.0f);
    } else {
        for (int i = base; i < e; i++) atomicAdd(&g_deg[dst[i]], 1.0f);
    }
    pdl_trigger();
}

// ---------------------------------------------------------------------------
// 2. dinv + pre-scaled features; acc1 INITIALIZED to xs (self-loop term)
__global__ void __launch_bounds__(256) k_prep(const float4* __restrict__ x, int n) {
    pdl_wait();
    int i = blockIdx.x * blockDim.x + threadIdx.x;
    if (i < n) {
        float di = rsqrtf(g_deg[i] + 1.0f);   // self-loop -> deg >= 1
        g_dinv[i] = di;
        float4 v = x[i];
        v.x *= di; v.y *= di; v.z *= di; v.w *= di;
        g_xs[i]   = v;
        g_acc1[i] = v;   // self-loop contribution pre-seeded
    }
    pdl_trigger();
}

// ---------------------------------------------------------------------------
// 3. layer-1 scatter: acc1[dst] += xs[src] — 4 edges/thread
__global__ void __launch_bounds__(256) k_scatter1(const int* __restrict__ src,
                                                  const int* __restrict__ dst, int e) {
    pdl_wait();
    int base = (blockIdx.x * blockDim.x + threadIdx.x) * 4;
    if (base + 4 <= e) {
        int4 s = *(const int4*)(src + base);
        int4 d = *(const int4*)(dst + base);
        float4 v0 = ldcg_f4(&g_xs[s.x]);
        float4 v1 = ldcg_f4(&g_xs[s.y]);
        float4 v2 = ldcg_f4(&g_xs[s.z]);
        float4 v3 = ldcg_f4(&g_xs[s.w]);
        red_v4(&g_acc1[d.x], v0);
        red_v4(&g_acc1[d.y], v1);
        red_v4(&g_acc1[d.z], v2);
        red_v4(&g_acc1[d.w], v3);
    } else {
        for (int i = base; i < e; i++)
            red_v4(&g_acc1[dst[i]], ldcg_f4(&g_xs[src[i]]));
    }
    pdl_trigger();
}

// ---------------------------------------------------------------------------
// 4. fused node transform [R11 loop shape, minus the xs read]:
//    a4 = dinv * acc1          (acc1 already includes self-loop)
//    gs = (relu(a4 W1 + b1) W2) * dinv
//    acc2 INITIALIZED to gs    (layer-2 self-loop term pre-seeded)
__global__ void __launch_bounds__(256) k_mid(const float* __restrict__ W1,   // [4,64]
                                             const float* __restrict__ b1,   // [64]
                                             const float* __restrict__ W2,   // [64,2]
                                             int n) {
    __shared__ float4 sA[32];   // {W1[0][j],W1[0][j+1], W1[1][j],W1[1][j+1]}
    __shared__ float4 sB[32];   // {W1[2][j],W1[2][j+1], W1[3][j],W1[3][j+1]}
    __shared__ float4 sC[32];   // {b1[j],b1[j+1], W2[j][0],W2[j+1][0]}
    __shared__ float2 sD[32];   // {W2[j][1], W2[j+1][1]}
    int t = threadIdx.x;
    if (t < 32) {
        int j = 2 * t;
        sA[t] = make_float4(W1[j],       W1[j + 1],       W1[64 + j],  W1[64 + j + 1]);
        sB[t] = make_float4(W1[128 + j], W1[128 + j + 1], W1[192 + j], W1[192 + j + 1]);
        sC[t] = make_float4(b1[j],       b1[j + 1],       W2[2 * j],   W2[2 * j + 2]);
        sD[t] = make_float2(W2[2 * j + 1], W2[2 * j + 3]);
    }
    pdl_wait();
    __syncthreads();

    int i = blockIdx.x * blockDim.x + t;
    if (i >= n) return;

    float di = g_dinv[i];
    float4 a = g_acc1[i];
    float a0 = di * a.x;
    float a1 = di * a.y;
    float a2 = di * a.z;
    float a3 = di * a.w;

    unsigned long long pa0, pa1, pa2, pa3, po0, po1;
    PACK2(pa0, a0, a0);
    PACK2(pa1, a1, a1);
    PACK2(pa2, a2, a2);
    PACK2(pa3, a3, a3);
    PACK2(po0, 0.f, 0.f);
    PACK2(po1, 0.f, 0.f);

#pragma unroll
    for (int j2 = 0; j2 < 32; j2++) {
        float4 A = sA[j2];
        float4 B = sB[j2];
        float4 C = sC[j2];
        float2 D = sD[j2];
        unsigned long long h2, w;
        PACK2(h2, C.x, C.y);                    // {b1[j], b1[j+1]}
        PACK2(w, A.x, A.y); FMA2(h2, pa0, w, h2);
        PACK2(w, A.z, A.w); FMA2(h2, pa1, w, h2);
        PACK2(w, B.x, B.y); FMA2(h2, pa2, w, h2);
        PACK2(w, B.z, B.w); FMA2(h2, pa3, w, h2);
        float hl, hh;
        UNPACK2(hl, hh, h2);                    // reg-pair alias, ~free
        hl = fmaxf(hl, 0.f);
        hh = fmaxf(hh, 0.f);
        PACK2(h2, hl, hh);
        PACK2(w, C.z, C.w); FMA2(po0, h2, w, po0);
        PACK2(w, D.x, D.y); FMA2(po1, h2, w, po1);
    }
    float p0l, p0h, p1l, p1h;
    UNPACK2(p0l, p0h, po0);
    UNPACK2(p1l, p1h, po1);
    float2 gs = make_float2((p0l + p0h) * di, (p1l + p1h) * di);

    g_gs[i]   = gs;
    g_acc2[i] = gs;   // self-loop contribution pre-seeded
    pdl_trigger();
}

// ---------------------------------------------------------------------------
// 5. layer-2 scatter: acc2[dst] += gs[src] — 4 edges/thread
__global__ void __launch_bounds__(256) k_scatter2(const int* __restrict__ src,
                                                  const int* __restrict__ dst, int e) {
    pdl_wait();
    int base = (blockIdx.x * blockDim.x + threadIdx.x) * 4;
    if (base + 4 <= e) {
        int4 s = *(const int4*)(src + base);
        int4 d = *(const int4*)(dst + base);
        float2 v0 = ldcg_f2(&g_gs[s.x]);
        float2 v1 = ldcg_f2(&g_gs[s.y]);
        float2 v2 = ldcg_f2(&g_gs[s.z]);
        float2 v3 = ldcg_f2(&g_gs[s.w]);
        red_v2(&g_acc2[d.x], v0);
        red_v2(&g_acc2[d.y], v1);
        red_v2(&g_acc2[d.z], v2);
        red_v2(&g_acc2[d.w], v3);
    } else {
        for (int i = base; i < e; i++)
            red_v2(&g_acc2[dst[i]], ldcg_f2(&g_gs[src[i]]));
    }
    pdl_trigger();
}

// ---------------------------------------------------------------------------
// 6. final: out = dinv * acc2 + b2 (acc2 already includes self-loop);
//    re-zeroes deg for the next run
__global__ void __launch_bounds__(256) k_final(const float* __restrict__ b2,
                                               float2* __restrict__ out, int n) {
    float bx = __ldg(&b2[0]);
    float by = __ldg(&b2[1]);
    pdl_wait();
    int i = blockIdx.x * blockDim.x + threadIdx.x;
    if (i < n) {
        float di = g_dinv[i];
        float2 a = g_acc2[i];
        out[i] = make_float2(di * a.x + bx, di * a.y + by);
        g_deg[i] = 0.0f;   // self-clean: ready for next invocation/replay
    }
}

// ---------------------------------------------------------------------------
// PDL launch helper
template <typename... Args>
static void pdl_launch(void (*kern)(Args...), int grid, int block,
                       Args... args) {
    cudaLaunchConfig_t cfg = {};
    cfg.gridDim  = dim3(grid, 1, 1);
    cfg.blockDim = dim3(block, 1, 1);
    cfg.dynamicSmemBytes = 0;
    cfg.stream = 0;
    cudaLaunchAttribute attr[1];
    attr[0].id = cudaLaunchAttributeProgrammaticStreamSerialization;
    attr[0].val.programmaticStreamSerializationAllowed = 1;
    cfg.attrs = attr;
    cfg.numAttrs = 1;
    cudaLaunchKernelEx(&cfg, kern, args...);
}

extern "C" void kernel_launch(void* const* d_in, const int* in_sizes, int n_in,
                              void* d_out, int out_size) {
    const float* x  = (const float*)d_in[0];   // [N,4]
    const int*   ei = (const int*)d_in[1];     // [2,E]  int32
    const float* W1 = (const float*)d_in[2];   // [4,64]
    const float* b1 = (const float*)d_in[3];   // [64]
    const float* W2 = (const float*)d_in[4];   // [64,2]
    const float* b2 = (const float*)d_in[5];   // [2]
    float2*      out = (float2*)d_out;         // [N,2]

    const int n = in_sizes[0] / 4;
    const int e = in_sizes[1] / 2;
    const int* src = ei;
    const int* dst = ei + e;

    const int T = 256;
    const int gn  = (n + T - 1) / T;
    const int ge4 = ((e + 3) / 4 + T - 1) / T;   // 4 edges/thread

    pdl_launch(k_deg,      ge4, T, dst, e);
    pdl_launch(k_prep,     gn,  T, (const float4*)x, n);
    pdl_launch(k_scatter1, ge4, T, src, dst, e);
    pdl_launch(k_mid,      gn,  T, W1, b1, W2, n);
    pdl_launch(k_scatter2, ge4, T, src, dst, e);
    pdl_launch(k_final,    gn,  T, b2, out, n);
}